// round 1
// baseline (speedup 1.0000x reference)
#include <cuda_runtime.h>

// LIFNeuron: dopri5(8 fixed steps) of dx = gelu(x@W) * 1/(1+sigmoid(x@Wg+bg)),
// then spike = (x(1) - 0.3 > 0). Stage 7 (k7) is dead in the reference (B5[6]==0)
// and is skipped: 48 dynamics evals total.
//
// One warp processes R=4 rows. W/Wg transposed in SMEM (pad 68 -> conflict-free
// float4 loads). Stage input xi broadcast via per-warp SMEM buffer.

#define NWARP 8
#define R 4
#define NTHREADS (NWARP * 32)
#define WS 68   // padded row stride for transposed weights (floats)

// h = 1/8 premultiplied into the tableau. 0.125f * fp32(a) is exact (exp shift),
// matching the reference's  h * float(np.float32(a)).
#define HC(x) (0.125f * (float)(x))

__device__ __forceinline__ float gelu_f(float z) {
    // exact gelu: 0.5*z*(1+erf(z/sqrt(2)))
    return 0.5f * z * (1.0f + erff(z * 0.70710678118654752440f));
}

__device__ __forceinline__ float timefac_f(float g) {
    // 1 / (1 + sigmoid(g)), sigmoid = 1/(1+exp(-g)); rcp.rn == correctly rounded div by 1
    float e = expf(-g);
    float s = __frcp_rn(1.0f + e);
    return __frcp_rn(1.0f + s);
}

// Evaluate k = f(xi) for R rows held by this warp.
// xi{0,1}[r] are the lane's two components (j=lane, j=lane+32) of row r's stage input.
__device__ __forceinline__ void eval_f(
    const float* __restrict__ sW, const float* __restrict__ sG,
    float (*__restrict__ xsw)[64], int lane, float bg0, float bg1,
    const float* __restrict__ xi0, const float* __restrict__ xi1,
    float* __restrict__ o0, float* __restrict__ o1)
{
    __syncwarp();   // prior-stage reads of xsw complete
    #pragma unroll
    for (int r = 0; r < R; r++) {
        xsw[r][lane]      = xi0[r];
        xsw[r][lane + 32] = xi1[r];
    }
    __syncwarp();

    float z0[R], z1[R], g0[R], g1[R];
    #pragma unroll
    for (int r = 0; r < R; r++) { z0[r] = 0.f; z1[r] = 0.f; g0[r] = 0.f; g1[r] = 0.f; }

    const float4* wa = (const float4*)(sW + lane * WS);
    const float4* wb = (const float4*)(sW + (lane + 32) * WS);
    const float4* va = (const float4*)(sG + lane * WS);
    const float4* vb = (const float4*)(sG + (lane + 32) * WS);

    #pragma unroll 4
    for (int q = 0; q < 16; q++) {
        float4 w0 = wa[q], w1 = wb[q], v0 = va[q], v1 = vb[q];
        #pragma unroll
        for (int r = 0; r < R; r++) {
            float4 xi = ((const float4*)xsw[r])[q];   // broadcast LDS.128
            z0[r] = fmaf(xi.x, w0.x, z0[r]);
            z0[r] = fmaf(xi.y, w0.y, z0[r]);
            z0[r] = fmaf(xi.z, w0.z, z0[r]);
            z0[r] = fmaf(xi.w, w0.w, z0[r]);
            z1[r] = fmaf(xi.x, w1.x, z1[r]);
            z1[r] = fmaf(xi.y, w1.y, z1[r]);
            z1[r] = fmaf(xi.z, w1.z, z1[r]);
            z1[r] = fmaf(xi.w, w1.w, z1[r]);
            g0[r] = fmaf(xi.x, v0.x, g0[r]);
            g0[r] = fmaf(xi.y, v0.y, g0[r]);
            g0[r] = fmaf(xi.z, v0.z, g0[r]);
            g0[r] = fmaf(xi.w, v0.w, g0[r]);
            g1[r] = fmaf(xi.x, v1.x, g1[r]);
            g1[r] = fmaf(xi.y, v1.y, g1[r]);
            g1[r] = fmaf(xi.z, v1.z, g1[r]);
            g1[r] = fmaf(xi.w, v1.w, g1[r]);
        }
    }

    #pragma unroll
    for (int r = 0; r < R; r++) {
        o0[r] = gelu_f(z0[r]) * timefac_f(g0[r] + bg0);
        o1[r] = gelu_f(z1[r]) * timefac_f(g1[r] + bg1);
    }
}

__global__ __launch_bounds__(NTHREADS, 2)
void lif_dopri5_kernel(const float* __restrict__ xin,
                       const float* __restrict__ W,
                       const float* __restrict__ Wg,
                       const float* __restrict__ bgp,
                       float* __restrict__ out,
                       int batch)
{
    __shared__ __align__(16) float sW[64 * WS];
    __shared__ __align__(16) float sG[64 * WS];
    __shared__ __align__(16) float sx[NWARP][R][64];

    const int tid = threadIdx.x;
    // load weights, transposed: sW[j*WS + k] = W[k][j]
    for (int i = tid; i < 4096; i += NTHREADS) {
        int k = i >> 6, j = i & 63;
        sW[j * WS + k] = W[i];
        sG[j * WS + k] = Wg[i];
    }
    __syncthreads();

    const int warp = tid >> 5;
    const int lane = tid & 31;
    float (*xsw)[64] = sx[warp];

    const int row0 = (blockIdx.x * NWARP + warp) * R;
    if (row0 >= batch) return;

    const float bg0 = bgp[lane];
    const float bg1 = bgp[lane + 32];

    float x0[R], x1[R];
    #pragma unroll
    for (int r = 0; r < R; r++) {
        int rr = (row0 + r < batch) ? (row0 + r) : (batch - 1);
        x0[r] = xin[rr * 64 + lane];
        x1[r] = xin[rr * 64 + lane + 32];
    }

    // dopri5 tableau * h (B5[1] == 0, B5[6] == 0 -> k7 never evaluated)
    const float A10 = HC(1.0 / 5.0);
    const float A20 = HC(3.0 / 40.0),      A21 = HC(9.0 / 40.0);
    const float A30 = HC(44.0 / 45.0),     A31 = HC(-56.0 / 15.0),    A32 = HC(32.0 / 9.0);
    const float A40 = HC(19372.0 / 6561.0), A41 = HC(-25360.0 / 2187.0),
                A42 = HC(64448.0 / 6561.0), A43 = HC(-212.0 / 729.0);
    const float A50 = HC(9017.0 / 3168.0),  A51 = HC(-355.0 / 33.0),
                A52 = HC(46732.0 / 5247.0), A53 = HC(49.0 / 176.0),
                A54 = HC(-5103.0 / 18656.0);
    const float B0 = HC(35.0 / 384.0), B2 = HC(500.0 / 1113.0), B3 = HC(125.0 / 192.0),
                B4 = HC(-2187.0 / 6784.0), B5c = HC(11.0 / 84.0);

    for (int step = 0; step < 8; step++) {
        float k1_0[R], k1_1[R], k2_0[R], k2_1[R], k3_0[R], k3_1[R];
        float k4_0[R], k4_1[R], k5_0[R], k5_1[R], k6_0[R], k6_1[R];
        float xi0[R], xi1[R];

        // stage 1: k1 = f(x)
        eval_f(sW, sG, xsw, lane, bg0, bg1, x0, x1, k1_0, k1_1);

        // stage 2
        #pragma unroll
        for (int r = 0; r < R; r++) {
            xi0[r] = fmaf(A10, k1_0[r], x0[r]);
            xi1[r] = fmaf(A10, k1_1[r], x1[r]);
        }
        eval_f(sW, sG, xsw, lane, bg0, bg1, xi0, xi1, k2_0, k2_1);

        // stage 3
        #pragma unroll
        for (int r = 0; r < R; r++) {
            float a = fmaf(A20, k1_0[r], x0[r]); xi0[r] = fmaf(A21, k2_0[r], a);
            float b = fmaf(A20, k1_1[r], x1[r]); xi1[r] = fmaf(A21, k2_1[r], b);
        }
        eval_f(sW, sG, xsw, lane, bg0, bg1, xi0, xi1, k3_0, k3_1);

        // stage 4
        #pragma unroll
        for (int r = 0; r < R; r++) {
            float a = fmaf(A30, k1_0[r], x0[r]);
            a = fmaf(A31, k2_0[r], a);
            xi0[r] = fmaf(A32, k3_0[r], a);
            float b = fmaf(A30, k1_1[r], x1[r]);
            b = fmaf(A31, k2_1[r], b);
            xi1[r] = fmaf(A32, k3_1[r], b);
        }
        eval_f(sW, sG, xsw, lane, bg0, bg1, xi0, xi1, k4_0, k4_1);

        // stage 5
        #pragma unroll
        for (int r = 0; r < R; r++) {
            float a = fmaf(A40, k1_0[r], x0[r]);
            a = fmaf(A41, k2_0[r], a);
            a = fmaf(A42, k3_0[r], a);
            xi0[r] = fmaf(A43, k4_0[r], a);
            float b = fmaf(A40, k1_1[r], x1[r]);
            b = fmaf(A41, k2_1[r], b);
            b = fmaf(A42, k3_1[r], b);
            xi1[r] = fmaf(A43, k4_1[r], b);
        }
        eval_f(sW, sG, xsw, lane, bg0, bg1, xi0, xi1, k5_0, k5_1);

        // stage 6
        #pragma unroll
        for (int r = 0; r < R; r++) {
            float a = fmaf(A50, k1_0[r], x0[r]);
            a = fmaf(A51, k2_0[r], a);
            a = fmaf(A52, k3_0[r], a);
            a = fmaf(A53, k4_0[r], a);
            xi0[r] = fmaf(A54, k5_0[r], a);
            float b = fmaf(A50, k1_1[r], x1[r]);
            b = fmaf(A51, k2_1[r], b);
            b = fmaf(A52, k3_1[r], b);
            b = fmaf(A53, k4_1[r], b);
            xi1[r] = fmaf(A54, k5_1[r], b);
        }
        eval_f(sW, sG, xsw, lane, bg0, bg1, xi0, xi1, k6_0, k6_1);

        // x_new = x + B0*k1 + B2*k3 + B3*k4 + B4*k5 + B5*k6  (same order as ref)
        #pragma unroll
        for (int r = 0; r < R; r++) {
            float a = fmaf(B0, k1_0[r], x0[r]);
            a = fmaf(B2, k3_0[r], a);
            a = fmaf(B3, k4_0[r], a);
            a = fmaf(B4, k5_0[r], a);
            x0[r] = fmaf(B5c, k6_0[r], a);
            float b = fmaf(B0, k1_1[r], x1[r]);
            b = fmaf(B2, k3_1[r], b);
            b = fmaf(B3, k4_1[r], b);
            b = fmaf(B4, k5_1[r], b);
            x1[r] = fmaf(B5c, k6_1[r], b);
        }
    }

    // spike = (x - 0.3 > 0) ? 1 : 0
    #pragma unroll
    for (int r = 0; r < R; r++) {
        int rr = row0 + r;
        if (rr < batch) {
            out[rr * 64 + lane]      = ((x0[r] - 0.3f) > 0.0f) ? 1.0f : 0.0f;
            out[rr * 64 + lane + 32] = ((x1[r] - 0.3f) > 0.0f) ? 1.0f : 0.0f;
        }
    }
}

extern "C" void kernel_launch(void* const* d_in, const int* in_sizes, int n_in,
                              void* d_out, int out_size)
{
    const float* x  = (const float*)d_in[0];   // [batch, 64]
    const float* W  = (const float*)d_in[1];   // [64, 64] ode_weight
    const float* Wg = (const float*)d_in[2];   // [64, 64] gate_w
    const float* bg = (const float*)d_in[3];   // [64]     gate_b
    float* out = (float*)d_out;

    int batch = in_sizes[0] / 64;
    int rows_per_block = NWARP * R;
    int grid = (batch + rows_per_block - 1) / rows_per_block;

    lif_dopri5_kernel<<<grid, NTHREADS>>>(x, W, Wg, bg, out, batch);
}